// round 16
// baseline (speedup 1.0000x reference)
#include <cuda_runtime.h>
#include <cuda_fp16.h>
#include <cstdint>

#define GRID  128
#define NTHR  1024
#define BSZ   128
#define TE    512
#define HD    256
#define MELD  80
#define RF    5
#define STEPS 200
#define G3    768

// ---- smem float-offset layout (206,848 B total) ------------------------------------
#define F_XS    0        // [256][32] activation staging
#define F_HS    8192     // [256][32]
#define F_SCR   16384    // 4608 fl: attn region / K-split partials
#define F_WATT  20992    // 6144 fl
#define F_WG1   27136    // 6144 fl
#define F_WG2   33280    // 6144 fl
#define F_WOUT  39424    // 4096 fl (zero-padded)
#define F_HALFB 43520    // fp16 region base (float offset)
#define H_WIH1  0        // 6144 halves
#define H_WIH2  6144     // 6144
#define H_PROJ  12288    // 4096
#define SMEM_FLOATS (43520 + 8192)
#define SMEM_BYTES  (SMEM_FLOATS * 4)

// ---------------- device scratch (step vectors transposed [dim][BSZ]) ----------------
__device__ __half g_w1h[(size_t)BSZ * TE * HD];
__device__ __half g_ench[(size_t)BSZ * TE * HD];
__device__ __half g_w2hf[HD * HD];                   // full fp16 w2 (for fused q)
__device__ float g_pre1[STEPS * BSZ * HD];
__device__ float g_xs[STEPS * BSZ * (HD / 2)];
__device__ float g_giatt[(size_t)STEPS * G3 * BSZ];  // [step][j][b]
__device__ float g_dbuf[2][HD * BSZ];
__device__ float g_h1buf[2][HD * BSZ];
__device__ float g_h2buf[2][HD * BSZ];
__device__ float g_ddot[HD * BSZ];
__device__ float g_p[HD * BSZ];
__device__ float g_in2[HD * BSZ];
__device__ float g_s[HD * BSZ];
__device__ unsigned g_bar_leaf[8];
__device__ unsigned g_bar_root;
__device__ unsigned g_bar_epoch;

// ---------------- helpers ------------------------------------------------------------
__device__ __forceinline__ float tanh_fast(float x) {
    float y; asm("tanh.approx.f32 %0, %1;" : "=f"(y) : "f"(x)); return y;
}
__device__ __forceinline__ float sigmoidf_(float x) { return 1.f / (1.f + __expf(-x)); }
__device__ __forceinline__ unsigned ld_acq(const unsigned* p) {
    unsigned v; asm volatile("ld.acquire.gpu.b32 %0, [%1];" : "=r"(v) : "l"(p)); return v;
}
__device__ __forceinline__ void gsync(unsigned target)
{
    __syncthreads();
    if (threadIdx.x == 0) {
        __threadfence();
        const int lf = blockIdx.x & 7;
        if (atomicAdd(&g_bar_leaf[lf], 1u) == 15u) {
            g_bar_leaf[lf] = 0u;
            __threadfence();
            if (atomicAdd(&g_bar_root, 1u) == 7u) {
                g_bar_root = 0u;
                __threadfence();
                atomicAdd(&g_bar_epoch, 1u);
            } else {
                while ((int)(ld_acq(&g_bar_epoch) - target) < 0) { }
            }
        } else {
            while ((int)(ld_acq(&g_bar_epoch) - target) < 0) { }
        }
    }
    __syncthreads();
}
__device__ __forceinline__ void fma_h8(const float4& wh, const float* x8, float& acc)
{
    const __half2* p = (const __half2*)&wh;
    const float2 f0 = __half22float2(p[0]), f1 = __half22float2(p[1]);
    const float2 f2 = __half22float2(p[2]), f3 = __half22float2(p[3]);
    acc = fmaf(f0.x, x8[0], acc); acc = fmaf(f0.y, x8[1], acc);
    acc = fmaf(f1.x, x8[2], acc); acc = fmaf(f1.y, x8[3], acc);
    acc = fmaf(f2.x, x8[4], acc); acc = fmaf(f2.y, x8[5], acc);
    acc = fmaf(f3.x, x8[6], acc); acc = fmaf(f3.y, x8[7], acc);
}

// ---------------- staging: src_t [K][128] -> smem [K][32] ----------------------------
__device__ __forceinline__ void stage_t(const float* __restrict__ src, int K,
                                        float* __restrict__ xs)
{
    const int b0 = (blockIdx.x & 3) << 5;
    const int n = K * 8;
    for (int idx = threadIdx.x; idx < n; idx += NTHR) {
        const int k = idx >> 3, q = idx & 7;
        *(float4*)(xs + k * 32 + 4 * q) = *(const float4*)(src + (size_t)k * BSZ + b0 + 4 * q);
    }
}

// ---------------- GRU: smem weights; 32 warps = 8 j x 4 K-quarters -------------------
__device__ void gru_t(const float* __restrict__ gi_t,
                      const float* __restrict__ WhhS,
                      const __half* __restrict__ WihS,
                      const float* __restrict__ bih, const float* __restrict__ bhh,
                      const float* __restrict__ Hs, const float* __restrict__ Xs,
                      float* __restrict__ Hnew_t, float* __restrict__ Sum_t,
                      float* __restrict__ part)
{
    const int w = threadIdx.x >> 5, lane = threadIdx.x & 31;
    const int wl = w & 7, up = w >> 3;                 // up in [0,4)
    const int j = (blockIdx.x >> 2) + (wl << 5);
    const int b = ((blockIdx.x & 3) << 5) + lane;

    const float4* Wr4 = (const float4*)WhhS + wl * 192 + up * 16;
    const float4* Wz4 = Wr4 + 64;
    const float4* Wn4 = Wr4 + 128;
    float hr = 0.f, hz = 0.f, hn = 0.f;
#pragma unroll 8
    for (int k4 = 0; k4 < 16; k4++) {
        const int kk = ((up << 4) + k4) << 2;
        const float4 a = Wr4[k4], c = Wz4[k4], d = Wn4[k4];
        const float h0 = Hs[(kk + 0) * 32 + lane];
        const float h1 = Hs[(kk + 1) * 32 + lane];
        const float h2 = Hs[(kk + 2) * 32 + lane];
        const float h3 = Hs[(kk + 3) * 32 + lane];
        hr = fmaf(a.x, h0, hr); hr = fmaf(a.y, h1, hr);
        hr = fmaf(a.z, h2, hr); hr = fmaf(a.w, h3, hr);
        hz = fmaf(c.x, h0, hz); hz = fmaf(c.y, h1, hz);
        hz = fmaf(c.z, h2, hz); hz = fmaf(c.w, h3, hz);
        hn = fmaf(d.x, h0, hn); hn = fmaf(d.y, h1, hn);
        hn = fmaf(d.z, h2, hn); hn = fmaf(d.w, h3, hn);
    }
    float xr = 0.f, xz = 0.f, xn = 0.f;
    if (WihS) {
        const float4* U4 = (const float4*)WihS;
        const int rb = wl * 96 + up * 8;
#pragma unroll 4
        for (int k8 = 0; k8 < 8; k8++) {
            const int kb = (up << 6) + (k8 << 3);
            float x8[8];
#pragma unroll
            for (int i = 0; i < 8; i++) x8[i] = Xs[(kb + i) * 32 + lane];
            fma_h8(U4[rb + k8], x8, xr);
            fma_h8(U4[rb + 32 + k8], x8, xz);
            fma_h8(U4[rb + 64 + k8], x8, xn);
        }
    }
    if (up) {
        float* pp = part + ((up - 1) * 48 + wl * 6) * 32 + lane;
        pp[0]   = hr; pp[32]  = hz; pp[64]  = hn;
        pp[96]  = xr; pp[128] = xz; pp[160] = xn;
    }
    __syncthreads();
    if (!up) {
#pragma unroll
        for (int s = 0; s < 3; s++) {
            const float* pp = part + (s * 48 + wl * 6) * 32 + lane;
            hr += pp[0]; hz += pp[32]; hn += pp[64];
            xr += pp[96]; xz += pp[128]; xn += pp[160];
        }
        float ir, iz, inn;
        if (gi_t) {
            ir  = gi_t[(size_t)j * BSZ + b];
            iz  = gi_t[(size_t)(j + HD) * BSZ + b];
            inn = gi_t[(size_t)(j + 2 * HD) * BSZ + b];
        } else {
            ir  = xr + bih[j];
            iz  = xz + bih[j + HD];
            inn = xn + bih[j + 2 * HD];
        }
        const float rg = sigmoidf_(ir + hr + bhh[j]);
        const float zg = sigmoidf_(iz + hz + bhh[j + HD]);
        const float ng = tanhf(inn + rg * (hn + bhh[j + 2 * HD]));
        const float hv = Hs[j * 32 + lane];
        const float val = (1.f - zg) * ng + zg * hv;
        Hnew_t[(size_t)j * BSZ + b] = val;
        if (Sum_t) Sum_t[(size_t)j * BSZ + b] = val + Xs[j * 32 + lane];
    }
    __syncthreads();
}

// ---------------- D: proj (fp16 smem, K=512): 32 warps = 4 jp x 8 K-splits -----------
__device__ void gemv_proj(const __half* __restrict__ WS, const float* __restrict__ bias,
                          const float* __restrict__ Xs, float* __restrict__ Y_t,
                          float* __restrict__ part)
{
    const int w = threadIdx.x >> 5, lane = threadIdx.x & 31;
    const int g = w & 3, ks = w >> 2;                 // ks in [0,8)
    const int jp = (blockIdx.x >> 2) + (g << 5);
    const int j0 = 2 * jp;
    const int b = ((blockIdx.x & 3) << 5) + lane;
    const float4* Wa = (const float4*)WS + (g * 2) * 64 + ks * 8;
    const float4* Wb = Wa + 64;
    float a0 = 0.f, a1 = 0.f;
#pragma unroll 4
    for (int k8 = 0; k8 < 8; k8++) {
        const int kb = (ks << 6) + (k8 << 3);
        float x8[8];
#pragma unroll
        for (int i = 0; i < 8; i++) x8[i] = Xs[(kb + i) * 32 + lane];
        fma_h8(Wa[k8], x8, a0);
        fma_h8(Wb[k8], x8, a1);
    }
    if (ks) {
        float* pp = part + ((ks - 1) * 4 + g) * 64 + lane;
        pp[0] = a0; pp[32] = a1;
    }
    __syncthreads();
    if (!ks) {
#pragma unroll
        for (int s = 0; s < 7; s++) {
            const float* pp = part + (s * 4 + g) * 64 + lane;
            a0 += pp[0]; a1 += pp[32];
        }
        Y_t[(size_t)j0 * BSZ + b]       = a0 + bias[j0];
        Y_t[(size_t)(j0 + 1) * BSZ + b] = a1 + bias[j0 + 1];
    }
    __syncthreads();
}

// ---------------- G: out rows (fp32 smem, zero-padded): 32 warps = 8 jp x 4 ks -------
__device__ void gemv_out(const float* __restrict__ WoutS, const float* __restrict__ bias,
                         const float* __restrict__ Xs, float* __restrict__ outp,
                         float* __restrict__ part)
{
    const int w = threadIdx.x >> 5, lane = threadIdx.x & 31;
    const int g = w & 7, ks = w >> 3;                 // ks in [0,4)
    const int jp = (blockIdx.x >> 2) + (g << 5);
    const bool valid = jp < 200;
    const int j0 = 2 * jp;
    const int b = ((blockIdx.x & 3) << 5) + lane;
    const float4* Wa = (const float4*)WoutS + (g * 2) * 64 + ks * 16;
    const float4* Wb = Wa + 64;
    float a0 = 0.f, a1 = 0.f;
#pragma unroll 8
    for (int k4 = 0; k4 < 16; k4++) {
        const int kk = ((ks << 4) + k4) << 2;
        const float4 wa = Wa[k4], wb = Wb[k4];
        const float x0 = Xs[(kk + 0) * 32 + lane];
        const float x1 = Xs[(kk + 1) * 32 + lane];
        const float x2 = Xs[(kk + 2) * 32 + lane];
        const float x3 = Xs[(kk + 3) * 32 + lane];
        a0 = fmaf(wa.x, x0, a0); a0 = fmaf(wa.y, x1, a0);
        a0 = fmaf(wa.z, x2, a0); a0 = fmaf(wa.w, x3, a0);
        a1 = fmaf(wb.x, x0, a1); a1 = fmaf(wb.y, x1, a1);
        a1 = fmaf(wb.z, x2, a1); a1 = fmaf(wb.w, x3, a1);
    }
    if (ks) { float* pp = part + ((ks - 1) * 8 + g) * 64 + lane; pp[0] = a0; pp[32] = a1; }
    __syncthreads();
    if (valid && !ks) {
#pragma unroll
        for (int s = 0; s < 3; s++) {
            const float* pp = part + (s * 8 + g) * 64 + lane;
            a0 += pp[0]; a1 += pp[32];
        }
        outp[(size_t)b * 80000 + j0]     = a0 + bias[j0];
        outp[(size_t)b * 80000 + j0 + 1] = a1 + bias[j0 + 1];
    }
    __syncthreads();
}

// ---------------- C': fused q-GEMV + scores + softmax + context (block = batch) ------
// scr layout: qs 0, vs 256, sexp 512, red 1024(32), pacc 1056(2048), ds 3104(256), qp 3360(768)
__device__ void attn_fused(const float* __restrict__ dcur,
                           const float* __restrict__ b2,
                           const float* __restrict__ vw, float vb0,
                           float* __restrict__ scr)
{
    float* qs   = scr;
    float* vs   = scr + 256;
    float* sexp = scr + 512;
    float* red  = scr + 1024;
    float* pacc = scr + 1056;
    float* ds   = scr + 3104;
    float* qp   = scr + 3360;
    const int tid = threadIdx.x, lane = tid & 31, wid = tid >> 5;
    const int b = blockIdx.x;

    if (tid < 256) ds[tid] = dcur[(size_t)tid * BSZ + b];
    else if (tid < 512) vs[tid - 256] = vw[tid - 256];
    __syncthreads();

    // q = d @ w2^T : 256 j x 4 K-quarters
    {
        const int j = tid & 255, ks = tid >> 8;
        const float4* W = (const float4*)g_w2hf + (size_t)j * 32 + ks * 8;
        float acc = 0.f;
#pragma unroll 4
        for (int k8 = 0; k8 < 8; k8++) {
            const int kb = (ks << 6) + (k8 << 3);
            float x8[8];
#pragma unroll
            for (int i = 0; i < 8; i++) x8[i] = ds[kb + i];
            fma_h8(W[k8], x8, acc);
        }
        if (ks) qp[(ks - 1) * 256 + j] = acc;
        __syncthreads();
        if (!ks) qs[j] = acc + qp[j] + qp[256 + j] + qp[512 + j] + b2[j];
    }
    __syncthreads();

    // scores: 32 warps x 16 t
    float2 q2[4], v2[4];
#pragma unroll
    for (int m = 0; m < 4; m++) {
        q2[m] = *(const float2*)(qs + 2 * (lane + m * 32));
        v2[m] = *(const float2*)(vs + 2 * (lane + m * 32));
    }
    const __half2* wb = (const __half2*)g_w1h + (size_t)b * TE * (HD / 2);
#pragma unroll 2
    for (int i = 0; i < 16; i++) {
        const int t = wid * 16 + i;
        const __half2* r2 = wb + (size_t)t * (HD / 2) + lane;
        float acc = 0.f;
#pragma unroll
        for (int m = 0; m < 4; m++) {
            float2 ww = __half22float2(r2[m * 32]);
            acc += v2[m].x * tanh_fast(ww.x + q2[m].x)
                 + v2[m].y * tanh_fast(ww.y + q2[m].y);
        }
        for (int o = 16; o; o >>= 1) acc += __shfl_down_sync(0xffffffffu, acc, o);
        if (lane == 0) sexp[t] = acc + vb0;
    }
    __syncthreads();

    // softmax over 512 (warps 0-15)
    float s_ = 0.f, e = 0.f;
    if (tid < 512) {
        s_ = sexp[tid];
        float m_ = s_;
        for (int o = 16; o; o >>= 1) m_ = fmaxf(m_, __shfl_xor_sync(0xffffffffu, m_, o));
        if (lane == 0) red[wid] = m_;
    }
    __syncthreads();
    if (tid < 512) {
        float mx = red[0];
#pragma unroll
        for (int k = 1; k < 16; k++) mx = fmaxf(mx, red[k]);
        e = __expf(s_ - mx);
        float ss = e;
        for (int o = 16; o; o >>= 1) ss += __shfl_xor_sync(0xffffffffu, ss, o);
        if (lane == 0) red[wid] = ss;
    }
    __syncthreads();
    if (tid < 512) {
        float sum = red[0];
#pragma unroll
        for (int k = 1; k < 16; k++) sum += red[k];
        sexp[tid] = e;
        if (tid == 0) red[24] = 1.f / sum;
    }
    __syncthreads();

    // context: 128 h2 x 8 t-chunks of 64
    const int h2 = tid & 127, grp = tid >> 7;
    const __half2* e2 = (const __half2*)g_ench
                      + ((size_t)b * TE + grp * 64) * (HD / 2) + h2;
    float ax = 0.f, ay = 0.f;
#pragma unroll 8
    for (int tt = 0; tt < 64; tt++) {
        const float2 v = __half22float2(e2[(size_t)tt * (HD / 2)]);
        const float u = sexp[grp * 64 + tt];
        ax = fmaf(u, v.x, ax); ay = fmaf(u, v.y, ay);
    }
    pacc[grp * 256 + h2 * 2]     = ax;
    pacc[grp * 256 + h2 * 2 + 1] = ay;
    __syncthreads();
    if (tid < 256) {
        float r = 0.f;
#pragma unroll
        for (int c = 0; c < 8; c++) r += pacc[c * 256 + tid];
        g_ddot[(size_t)tid * BSZ + b] = r * red[24];
    }
    __syncthreads();
}

// ---------------- prelude tiled GEMM: 32 warps x 2 cols ------------------------------
__device__ void dev_linear(const float* __restrict__ X, const float* __restrict__ dec,
                           int nf4, const float* __restrict__ W,
                           const float* __restrict__ bias,
                           float* __restrict__ Yf, __half* __restrict__ Yh,
                           int ldy, int relu, int nrt, int ncp, float4* sm4, int tmode)
{
    const int tid = threadIdx.x, lane = tid & 31, wid = tid >> 5;
    const int stride4 = nf4 + 1;
    const int tiles = nrt * ncp;
    for (int t = blockIdx.x; t < tiles; t += GRID) {
        const int rt = t / ncp, cp = t - rt * ncp;
        const long r0 = (long)rt * 32;
        for (int idx = tid; idx < 32 * nf4; idx += NTHR) {
            int row = idx / nf4, c4 = idx - row * nf4;
            long r = r0 + row;
            float4 v;
            if (dec) v = *(const float4*)(dec + (r & 127) * 80000L
                                          + (r >> 7) * (RF * MELD) + c4 * 4);
            else     v = *(const float4*)(X + r * (long)(nf4 * 4) + c4 * 4);
            sm4[row * stride4 + c4] = v;
        }
        __syncthreads();
        const int j0 = cp * 64 + wid * 2;
        const float4* W0 = (const float4*)W + (size_t)j0 * nf4;
        const float4* W1 = W0 + nf4;
        const float4* xr = sm4 + lane * stride4;
        float a0 = bias[j0], a1 = bias[j0 + 1];
#pragma unroll 4
        for (int k = 0; k < nf4; k++) {
            const float4 x = xr[k];
            const float4 w0 = W0[k];
            a0 = fmaf(w0.x, x.x, a0); a0 = fmaf(w0.y, x.y, a0);
            a0 = fmaf(w0.z, x.z, a0); a0 = fmaf(w0.w, x.w, a0);
            const float4 w1 = W1[k];
            a1 = fmaf(w1.x, x.x, a1); a1 = fmaf(w1.y, x.y, a1);
            a1 = fmaf(w1.z, x.z, a1); a1 = fmaf(w1.w, x.w, a1);
        }
        if (relu) { a0 = fmaxf(a0, 0.f); a1 = fmaxf(a1, 0.f); }
        const long r = r0 + lane;
        if (tmode) {
            const size_t baseo = (size_t)(r >> 7) * (G3 * BSZ) + (r & 127);
            Yf[baseo + (size_t)j0 * BSZ]       = a0;
            Yf[baseo + (size_t)(j0 + 1) * BSZ] = a1;
        } else if (Yh) {
            const long orow = r * (long)ldy + j0;
            Yh[orow] = __float2half(a0); Yh[orow + 1] = __float2half(a1);
        } else {
            const long orow = r * (long)ldy + j0;
            Yf[orow] = a0; Yf[orow + 1] = a1;
        }
        __syncthreads();
    }
}

// ---------------- persistent kernel --------------------------------------------------
__global__ void __launch_bounds__(NTHR, 1)
mel_persist(const float* __restrict__ enc, const float* __restrict__ dec,
            const float* pre_w1, const float* pre_b1,
            const float* pre_w2, const float* pre_b2,
            const float* w1, const float* b1, const float* w2, const float* b2,
            const float* v_w, const float* v_b,
            const float* proj_w, const float* proj_b,
            const float* out_w, const float* out_b,
            const float* att_wih, const float* att_whh,
            const float* att_bih, const float* att_bhh,
            const float* g1_wih, const float* g1_whh,
            const float* g1_bih, const float* g1_bhh,
            const float* g2_wih, const float* g2_whh,
            const float* g2_bih, const float* g2_bhh,
            float* __restrict__ out)
{
    extern __shared__ float smf[];
    float* xs  = smf + F_XS;
    float* hs  = smf + F_HS;
    float* scr = smf + F_SCR;
    __half* hb = (__half*)(smf + F_HALFB);
    const int tid = threadIdx.x;
    const unsigned base = ld_acq(&g_bar_epoch);
    unsigned ep = 0;
#define GS() gsync(base + (++ep))

    // P0: zero states + fp16 copies
    {
        const int gtid = blockIdx.x * NTHR + tid;
        for (int i = gtid; i < HD * BSZ; i += GRID * NTHR) {
            g_dbuf[0][i] = 0.f;  g_dbuf[1][i] = 0.f;
            g_h1buf[0][i] = 0.f; g_h1buf[1][i] = 0.f;
            g_h2buf[0][i] = 0.f; g_h2buf[1][i] = 0.f;
        }
        const float4* e4 = (const float4*)enc;
        __half2* o2 = (__half2*)g_ench;
        const int n4 = (BSZ * TE * HD) / 4;
        for (int i = gtid; i < n4; i += GRID * NTHR) {
            const float4 v = e4[i];
            o2[2 * i]     = __floats2half2_rn(v.x, v.y);
            o2[2 * i + 1] = __floats2half2_rn(v.z, v.w);
        }
        for (int i = gtid; i < HD * HD; i += GRID * NTHR)
            g_w2hf[i] = __float2half(w2[i]);
    }
    // P1..P4 prelude GEMMs
    dev_linear(nullptr, dec, 20, pre_w1, pre_b1, g_pre1, nullptr, HD, 1, 800, 4, (float4*)smf, 0);
    GS();
    dev_linear(g_pre1, nullptr, 64, pre_w2, pre_b2, g_xs, nullptr, 128, 1, 800, 2, (float4*)smf, 0);
    GS();
    dev_linear(g_xs, nullptr, 32, att_wih, att_bih, g_giatt, nullptr, 0, 0, 800, 12, (float4*)smf, 1);
    GS();
    dev_linear(enc, nullptr, 64, w1, b1, nullptr, g_w1h, HD, 0, 2048, 4, (float4*)smf, 0);
    GS();

    // ---- load this block's fixed j-slice weights into smem (once) -------------------
    {
        const int js = blockIdx.x >> 2;
        for (int idx = tid; idx < 6144; idx += NTHR) {
            const int wl = idx / 768, rem = idx - wl * 768;
            const int gr = rem >> 8, k = rem & 255;
            const size_t row = (size_t)(js + (wl << 5) + (gr << 8));
            smf[F_WATT + idx] = att_whh[row * 256 + k];
            smf[F_WG1  + idx] = g1_whh[row * 256 + k];
            smf[F_WG2  + idx] = g2_whh[row * 256 + k];
            hb[H_WIH1 + idx]  = __float2half(g1_wih[row * 256 + k]);
            hb[H_WIH2 + idx]  = __float2half(g2_wih[row * 256 + k]);
        }
        for (int idx = tid; idx < 4096; idx += NTHR) {
            const int g = idx >> 10, r = (idx >> 9) & 1, k = idx & 511;
            const int j = 2 * (js + (g << 5)) + r;
            hb[H_PROJ + idx] = __float2half(proj_w[(size_t)j * 512 + k]);
        }
        for (int idx = tid; idx < 4096; idx += NTHR) {
            const int g = idx >> 9, r = (idx >> 8) & 1, k = idx & 255;
            const int jp = js + (g << 5);
            smf[F_WOUT + idx] = (jp < 200) ? out_w[(size_t)(2 * jp + r) * 256 + k] : 0.f;
        }
    }
    const float vb0 = v_b[0];
    __syncthreads();

    for (int i = 0; i < STEPS; i++) {
        const int cur = i & 1, prev = cur ^ 1;

        // A: attention GRU (gi precomputed; Whh from smem)
        stage_t(g_dbuf[prev], 256, xs);
        __syncthreads();
        gru_t(g_giatt + (size_t)i * G3 * BSZ, smf + F_WATT, nullptr,
              nullptr, att_bhh, xs, nullptr, g_dbuf[cur], nullptr, scr);
        GS();
        // C': fused q + scores + softmax + context
        attn_fused(g_dbuf[cur], b2, v_w, vb0, scr);
        GS();
        // D: p = [d | ddot] @ proj^T (stage d into xs rows 0-255, ddot into 256-511)
        stage_t(g_dbuf[cur], 256, xs);
        stage_t(g_ddot, 256, hs);
        __syncthreads();
        gemv_proj(hb + H_PROJ, proj_b, xs, g_p, scr);
        GS();
        // E: GRU1; in2 = p + o1
        stage_t(g_p, 256, xs);
        stage_t(g_h1buf[prev], 256, hs);
        __syncthreads();
        gru_t(nullptr, smf + F_WG1, hb + H_WIH1, g1_bih, g1_bhh,
              hs, xs, g_h1buf[cur], g_in2, scr);
        GS();
        // F: GRU2; s = in2 + o2
        stage_t(g_in2, 256, xs);
        stage_t(g_h2buf[prev], 256, hs);
        __syncthreads();
        gru_t(nullptr, smf + F_WG2, hb + H_WIH2, g2_bih, g2_bhh,
              hs, xs, g_h2buf[cur], g_s, scr);
        GS();
        // G: out rows (no grid barrier; next-A write target is disjoint)
        stage_t(g_s, 256, xs);
        __syncthreads();
        gemv_out(smf + F_WOUT, out_b, xs, out + (size_t)i * RF * MELD, scr);
    }
#undef GS
}

// ---------------- host launch --------------------------------------------------------
extern "C" void kernel_launch(void* const* d_in, const int* in_sizes, int n_in,
                              void* d_out, int out_size)
{
    cudaFuncSetAttribute(mel_persist, cudaFuncAttributeMaxDynamicSharedMemorySize,
                         SMEM_BYTES);
    mel_persist<<<GRID, NTHR, SMEM_BYTES>>>(
        (const float*)d_in[0],  (const float*)d_in[1],
        (const float*)d_in[2],  (const float*)d_in[3],
        (const float*)d_in[4],  (const float*)d_in[5],
        (const float*)d_in[6],  (const float*)d_in[7],
        (const float*)d_in[8],  (const float*)d_in[9],
        (const float*)d_in[10], (const float*)d_in[11],
        (const float*)d_in[12], (const float*)d_in[13],
        (const float*)d_in[14], (const float*)d_in[15],
        (const float*)d_in[16], (const float*)d_in[17],
        (const float*)d_in[18], (const float*)d_in[19],
        (const float*)d_in[20], (const float*)d_in[21],
        (const float*)d_in[22], (const float*)d_in[23],
        (const float*)d_in[24], (const float*)d_in[25],
        (const float*)d_in[26], (const float*)d_in[27],
        (float*)d_out);
}